// round 10
// baseline (speedup 1.0000x reference)
#include <cuda_runtime.h>
#include <cuda_fp16.h>
#include <cstdint>

#define B_  4
#define S_  2048
#define D_  1024
#define H_  16
#define DH  64

// Scratch (device globals -- no allocations allowed).
// k-dims stored with perm16: within each 16-block, memory position
// 4t+r (t=0..3, r=0..3) holds dim 2t + r + (r>=2 ? 6 : 0).
__device__ __half g_qh[(size_t)B_*H_*S_*DH];     // perm16 q
__device__ __half g_kh[(size_t)B_*H_*S_*DH];     // perm16 k
__device__ __half g_xh[(size_t)B_*S_*D_];        // perm16 x (also serves as V)
__device__ __half g_wh[(size_t)2*D_*D_];         // perm16 W
__device__ float  g_kpart[256*64];
__device__ float  g_ksum[B_*H_*DH];              // perm16 layout

// ---------------------------------------------------------------------------
// helpers
// ---------------------------------------------------------------------------
__device__ __forceinline__ uint32_t smem_u32(const void* p) {
    uint32_t a;
    asm("{ .reg .u64 t; cvta.to.shared.u64 t, %1; cvt.u32.u64 %0, t; }"
        : "=r"(a) : "l"(p));
    return a;
}
#define CP_ASYNC16(dst, src) \
    asm volatile("cp.async.cg.shared.global [%0], [%1], 16;" :: "r"(dst), "l"(src) : "memory")
#define CP_COMMIT() asm volatile("cp.async.commit_group;" ::: "memory")
#define CP_WAIT(N)  asm volatile("cp.async.wait_group %0;" :: "n"(N) : "memory")

#define LDSM_X4_TRANS(r0, r1, r2, r3, addr) \
    asm volatile("ldmatrix.sync.aligned.m8n8.x4.trans.shared.b16 {%0,%1,%2,%3}, [%4];" \
        : "=r"(r0), "=r"(r1), "=r"(r2), "=r"(r3) : "r"(addr))

// fp16 mma m16n8k16 (row.col), fp32 accum, D += A*B
__device__ __forceinline__ void mma_f16(float* d, const uint32_t* a, const uint32_t* b)
{
    asm volatile(
        "mma.sync.aligned.m16n8k16.row.col.f32.f16.f16.f32 "
        "{%0,%1,%2,%3}, {%4,%5,%6,%7}, {%8,%9}, {%0,%1,%2,%3};"
        : "+f"(d[0]), "+f"(d[1]), "+f"(d[2]), "+f"(d[3])
        : "r"(a[0]), "r"(a[1]), "r"(a[2]), "r"(a[3]), "r"(b[0]), "r"(b[1]));
}

__device__ __forceinline__ float selu_f(float s)
{
    return (s > 0.f) ? 1.0507009873554805f * s
                     : 1.7580993408473766f * (__expf(s) - 1.f);
}

__device__ __forceinline__ uint32_t packh2(float lo, float hi)
{
    __half2 h = __floats2half2_rn(lo, hi);
    return *reinterpret_cast<uint32_t*>(&h);
}

__device__ __forceinline__ int orig16(int r)    // perm16 inverse map
{
    const int t = r >> 2, m = r & 3;
    return 2 * t + m + ((m >= 2) ? 6 : 0);
}

// ---------------------------------------------------------------------------
// Kernel 0: fp16 + perm16 convert x and W
// ---------------------------------------------------------------------------
#define XB16 ((size_t)B_*S_*D_/16)       // 524288
#define WB16 ((size_t)2*D_*D_/16)        // 131072

__global__ __launch_bounds__(256) void cvt_kernel(
    const float* __restrict__ x, const float* __restrict__ W)
{
    const size_t i = (size_t)blockIdx.x * 256 + threadIdx.x;
    const float* src; __half* dst;
    if (i < XB16)              { src = x + i * 16;           dst = g_xh + i * 16; }
    else if (i < XB16 + WB16)  { src = W + (i - XB16) * 16;  dst = g_wh + (i - XB16) * 16; }
    else return;
    float v[16];
#pragma unroll
    for (int q = 0; q < 4; q++) *(float4*)&v[q*4] = *(const float4*)(src + q*4);
    __half h[16];
#pragma unroll
    for (int q = 0; q < 16; q++) h[q] = __float2half(v[orig16(q)]);
    *(uint4*)dst       = *(uint4*)&h[0];
    *(uint4*)(dst + 8) = *(uint4*)&h[8];
}

// ---------------------------------------------------------------------------
// Kernel 1: fused q/k projection, fp16 m16n8k16, 3-stage, 1 sync per chunk.
// ---------------------------------------------------------------------------
#define PJ_LDH   48                          // halves per row (96 B)
#define PJ_MAT_B (128 * 96)                  // 12288 B per matrix per stage
#define PJ_STG_B (2 * PJ_MAT_B)              // 24576 B per stage
#define PJ_SMEM  73728                       // 3 stages (>= Cs 67584)
#define PJ_LDC   132

__global__ __launch_bounds__(256, 2) void proj_kernel(const float* __restrict__ bias)
{
    extern __shared__ char smc[];
    float* Cs = (float*)smc;
    __shared__ float sBias[128];

    const int tid = threadIdx.x;
    const int m0 = blockIdx.y * 128;
    const int n0 = blockIdx.x * 128;
    const int wid = tid >> 5;
    const int lane = tid & 31;
    const int gid = lane >> 2;
    const int tig = lane & 3;
    const int wm = wid & 1;
    const int wn = wid >> 1;

    if (tid < 128) sBias[tid] = bias[n0 + tid];

    float acc[4][4][4];
#pragma unroll
    for (int mi = 0; mi < 4; mi++)
#pragma unroll
        for (int ni = 0; ni < 4; ni++)
#pragma unroll
            for (int r = 0; r < 4; r++) acc[mi][ni][r] = 0.f;

    const uint32_t sbase = smem_u32(smc);

    auto load_stage = [&](int s, int k0) {
        const uint32_t aB = sbase + s * PJ_STG_B;
        const uint32_t bB = aB + PJ_MAT_B;
#pragma unroll
        for (int i = 0; i < 2; i++) {
            const int idx = tid + i * 256;
            const int row = idx >> 2, c = idx & 3;
            CP_ASYNC16(aB + row * 96 + c * 16,
                       g_xh + (size_t)(m0 + row) * D_ + k0 + c * 8);
        }
#pragma unroll
        for (int i = 0; i < 2; i++) {
            const int idx = tid + i * 256;
            const int row = idx >> 2, c = idx & 3;
            CP_ASYNC16(bB + row * 96 + c * 16,
                       g_wh + (size_t)(n0 + row) * D_ + k0 + c * 8);
        }
        CP_COMMIT();
    };

    load_stage(0, 0);
    load_stage(1, 32);

    const int NKC = D_ / 32;                 // 32 chunks
    for (int kc = 0; kc < NKC; kc++) {
        if (kc < NKC - 1) CP_WAIT(1); else CP_WAIT(0);
        __syncthreads();
        if (kc + 2 < NKC) load_stage((kc + 2) % 3, (kc + 2) * 32);

        const __half* A  = (const __half*)(smc + (kc % 3) * PJ_STG_B);
        const __half* Bp = A + 128 * PJ_LDH;
#pragma unroll
        for (int kg = 0; kg < 2; kg++) {
            uint32_t a[4][4];
#pragma unroll
            for (int mi = 0; mi < 4; mi++) {
                const __half* ra = A + (wm * 64 + mi * 16 + gid) * PJ_LDH + kg * 16 + tig * 4;
                uint2 lo = *(const uint2*)ra;
                uint2 hi = *(const uint2*)(ra + 8 * PJ_LDH);
                a[mi][0] = lo.x; a[mi][1] = hi.x; a[mi][2] = lo.y; a[mi][3] = hi.y;
            }
            uint32_t bf[4][2];
#pragma unroll
            for (int ni = 0; ni < 4; ni++) {
                const __half* rb = Bp + (wn * 32 + ni * 8 + gid) * PJ_LDH + kg * 16 + tig * 4;
                uint2 f = *(const uint2*)rb;
                bf[ni][0] = f.x; bf[ni][1] = f.y;
            }
#pragma unroll
            for (int mi = 0; mi < 4; mi++)
#pragma unroll
                for (int ni = 0; ni < 4; ni++)
                    mma_f16(acc[mi][ni], a[mi], bf[ni]);
        }
    }
    __syncthreads();

    // ---- epilogue: acc -> Cs -> perm16 fp16 scatter to g_qh / g_kh ----
#pragma unroll
    for (int mi = 0; mi < 4; mi++)
#pragma unroll
        for (int ni = 0; ni < 4; ni++) {
            const int r = wm * 64 + mi * 16 + gid;
            const int c = wn * 32 + ni * 8 + 2 * tig;
            *(float2*)&Cs[r * PJ_LDC + c]       = make_float2(acc[mi][ni][0], acc[mi][ni][1]);
            *(float2*)&Cs[(r + 8) * PJ_LDC + c] = make_float2(acc[mi][ni][2], acc[mi][ni][3]);
        }
    __syncthreads();

    {
        const int r    = tid >> 1;
        const int hsel = tid & 1;
        const int m = m0 + r;
        const int bb = m >> 11;
        const int s_idx = m & 2047;
        const int hh = n0 >> 7;
        const size_t base = (((size_t)bb * H_ + hh) * S_ + s_idx) * DH;
        const float* cr = Cs + r * PJ_LDC;
#pragma unroll
        for (int bi = 0; bi < 2; bi++) {
            const int bk = hsel * 2 + bi;        // d-block of 16
            __half qh[16], kh[16];
#pragma unroll
            for (int q = 0; q < 16; q++) {
                const int dorig = bk * 16 + orig16(q);
                qh[q] = __float2half(cr[2 * dorig]     + sBias[2 * dorig]);
                kh[q] = __float2half(cr[2 * dorig + 1] + sBias[2 * dorig + 1]);
            }
            *(uint4*)(g_qh + base + bk * 16)     = *(uint4*)&qh[0];
            *(uint4*)(g_qh + base + bk * 16 + 8) = *(uint4*)&qh[8];
            *(uint4*)(g_kh + base + bk * 16)     = *(uint4*)&kh[0];
            *(uint4*)(g_kh + base + bk * 16 + 8) = *(uint4*)&kh[8];
        }
    }
}

// ---------------------------------------------------------------------------
// Kernel 2a/2b: ksum (perm16 layout flows through)
// ---------------------------------------------------------------------------
__global__ __launch_bounds__(256) void ksum1_kernel()
{
    __shared__ float red[256];
    const int blk = blockIdx.x;
    const int bh = blk >> 2, c = blk & 3;
    const int t = threadIdx.x;
    const int d = t & 63;
    const int sub = t >> 6;
    const __half* base = g_kh + (size_t)bh * S_ * DH;
    const int j0 = c * 512 + sub * 128, j1 = j0 + 128;
    float s = 0.f;
    for (int j = j0; j < j1; j++) s += __half2float(base[(size_t)j * DH + d]);
    red[t] = s;
    __syncthreads();
    if (t < 64)
        g_kpart[blk * 64 + t] = red[t] + red[64 + t] + red[128 + t] + red[192 + t];
}

__global__ __launch_bounds__(64) void ksum2_kernel()
{
    const int bh = blockIdx.x;
    const int d = threadIdx.x;
    g_ksum[bh * 64 + d] = g_kpart[(bh * 4 + 0) * 64 + d] + g_kpart[(bh * 4 + 1) * 64 + d]
                        + g_kpart[(bh * 4 + 2) * 64 + d] + g_kpart[(bh * 4 + 3) * 64 + d];
}

// ---------------------------------------------------------------------------
// Kernel 3: fused attention, fp16 m16n8k16, 3-stage pipeline.
// 256 threads, 2 CTAs/SM.  8 warps: wm = wid (16 q-rows, full j=64 per iter).
// V loaded directly from g_xh (natural j rows); AV B-frags via
// ldmatrix.x4.trans; output d-columns un-permuted in the epilogue.
// smem: qs 128x80h (20480) @0, ks 3x64x80h (30720) @20480,
//       vs 3x64x72h (27648) @51200; ps overlays qs/ks post-loop.
// ---------------------------------------------------------------------------
#define AT_LDQ  80
#define AT_LDV  72
#define AT_KS_B (64 * AT_LDQ * 2)            // 10240 per stage
#define AT_VS_B (64 * AT_LDV * 2)            // 9216 per stage
#define AT_KS_OFF 20480
#define AT_VS_OFF 51200
#define AT_SMEM  78848

__global__ __launch_bounds__(256, 2) void attn_kernel(float* __restrict__ out)
{
    extern __shared__ char smc[];
    __half* qs = (__half*)smc;
    float*  ps = (float*)smc;                // overlay, post-loop only
    __shared__ float sKsum[64];
    __shared__ float sMrow[128];

    const int b  = blockIdx.z;
    const int h  = blockIdx.y;
    const int s0 = blockIdx.x * 128;
    const int tid = threadIdx.x;
    const int wid = tid >> 5;
    const int lane = tid & 31;
    const int gid = lane >> 2;
    const int tig = lane & 3;
    const int wm = wid;

    const size_t bh = (size_t)b * H_ + h;
    const __half* qg = g_qh + bh * S_ * DH;
    const __half* kg = g_kh + bh * S_ * DH;
    const __half* xv = g_xh + ((size_t)b * S_) * D_ + h * 64;   // V rows

    const uint32_t qsB = smem_u32(smc);
    const uint32_t ksB = qsB + AT_KS_OFF;
    const uint32_t vsB = qsB + AT_VS_OFF;

    auto load_kv = [&](int buf, int j0) {
        const uint32_t kB = ksB + buf * AT_KS_B;
        const uint32_t vB = vsB + buf * AT_VS_B;
#pragma unroll
        for (int i = 0; i < 2; i++) {
            const int idx = tid + i * 256;
            const int row = idx >> 3, c = idx & 7;
            CP_ASYNC16(kB + row * 160 + c * 16,
                       kg + (size_t)(j0 + row) * DH + c * 8);
        }
#pragma unroll
        for (int i = 0; i < 2; i++) {
            const int idx = tid + i * 256;
            const int row = idx >> 3, c = idx & 7;   // natural j row
            CP_ASYNC16(vB + row * 144 + c * 16,
                       xv + (size_t)(j0 + row) * D_ + c * 8);
        }
        CP_COMMIT();
    };

    // ---- prologue: Q + stage0, stage1 ----
#pragma unroll
    for (int i = 0; i < 4; i++) {
        const int idx = tid + i * 256;
        const int row = idx >> 3, c = idx & 7;
        CP_ASYNC16(qsB + row * 160 + c * 16,
                   qg + (size_t)(s0 + row) * DH + c * 8);
    }
    load_kv(0, 0);                           // G0 (includes Q)
    load_kv(1, 64);                          // G1
    if (tid < 64) sKsum[tid] = g_ksum[bh * DH + tid];
    CP_WAIT(1);                              // G0 done -> Q ready
    __syncthreads();

    const float SCALE = 0.125f;
    if (tid < 128) {
        float s = 0.f;
        const __half* qr = qs + tid * AT_LDQ;
#pragma unroll
        for (int d = 0; d < DH; d++) s += __half2float(qr[d]) * sKsum[d];
        sMrow[tid] = s * (SCALE / (float)S_);
    }
    __syncthreads();

    const float mr0 = sMrow[wm * 16 + gid];
    const float mr1 = sMrow[wm * 16 + gid + 8];

    float oacc[8][4];
#pragma unroll
    for (int nt = 0; nt < 8; nt++)
#pragma unroll
        for (int r = 0; r < 4; r++) oacc[nt][r] = 0.f;

    const int vgrp = lane >> 3;              // 0..3
    const int vrow = lane & 7;

    const int NJT = S_ / 64;                 // 32
    for (int jt = 0; jt < NJT; jt++) {
        const int buf = jt % 3;
        if (jt < NJT - 1) CP_WAIT(1); else CP_WAIT(0);
        __syncthreads();
        if (jt + 2 < NJT) load_kv((jt + 2) % 3, (jt + 2) * 64);

        const __half* kss = (const __half*)(smc + AT_KS_OFF + buf * AT_KS_B);
        const uint32_t vbase = vsB + buf * AT_VS_B;

        // ---- P = Q K^T : 16m x 64j ----
        float d[8][4];
#pragma unroll
        for (int tn = 0; tn < 8; tn++)
#pragma unroll
            for (int r = 0; r < 4; r++) d[tn][r] = 0.f;

#pragma unroll
        for (int g = 0; g < 4; g++) {
            const __half* ra = qs + (wm * 16 + gid) * AT_LDQ + g * 16 + tig * 4;
            uint2 lo = *(const uint2*)ra;
            uint2 hi = *(const uint2*)(ra + 8 * AT_LDQ);
            uint32_t a[4] = { lo.x, hi.x, lo.y, hi.y };
#pragma unroll
            for (int tn = 0; tn < 8; tn++) {
                const __half* rb = kss + (tn * 8 + gid) * AT_LDQ + g * 16 + tig * 4;
                uint2 f = *(const uint2*)rb;
                uint32_t bb2[2] = { f.x, f.y };
                mma_f16(d[tn], a, bb2);
            }
        }

        // ---- selu in regs; pack acc pairs directly into AV A-fragments ----
        uint32_t av[4][4];
#pragma unroll
        for (int u = 0; u < 4; u++) {
            const float e00 = selu_f(d[2*u][0]   * SCALE - mr0);
            const float e01 = selu_f(d[2*u][1]   * SCALE - mr0);
            const float e10 = selu_f(d[2*u][2]   * SCALE - mr1);
            const float e11 = selu_f(d[2*u][3]   * SCALE - mr1);
            const float f00 = selu_f(d[2*u+1][0] * SCALE - mr0);
            const float f01 = selu_f(d[2*u+1][1] * SCALE - mr0);
            const float f10 = selu_f(d[2*u+1][2] * SCALE - mr1);
            const float f11 = selu_f(d[2*u+1][3] * SCALE - mr1);
            av[u][0] = packh2(e00, e01);
            av[u][1] = packh2(e10, e11);
            av[u][2] = packh2(f00, f01);
            av[u][3] = packh2(f10, f11);
        }

        // ---- oacc += A @ V ; V B-frags via ldmatrix.x4.trans ----
#pragma unroll
        for (int u = 0; u < 4; u++) {
#pragma unroll
            for (int ntp = 0; ntp < 4; ntp++) {
                const uint32_t addr = vbase
                    + (u * 16 + (vgrp & 1) * 8 + vrow) * (AT_LDV * 2)
                    + ((2 * ntp + (vgrp >> 1)) * 8) * 2;
                uint32_t f0, f1, f2, f3;
                LDSM_X4_TRANS(f0, f1, f2, f3, addr);
                uint32_t b0[2] = { f0, f1 };
                uint32_t b1[2] = { f2, f3 };
                mma_f16(oacc[2*ntp],     av[u], b0);
                mma_f16(oacc[2*ntp + 1], av[u], b1);
            }
        }
    }

    // ---- epilogue: oacc -> ps (un-permuting d columns) -> gmem ----
    __syncthreads();
#pragma unroll
    for (int nt = 0; nt < 8; nt++) {
        const int p = nt * 8 + 2 * tig;              // perm position
        const int p15 = p & 15;
        const int ocol = (p & ~15) + 2 * (p15 >> 2) + ((p15 & 2) ? 8 : 0);
        *(float2*)(ps + (wm * 16 + gid) * 68 + ocol) =
            make_float2(oacc[nt][0], oacc[nt][1]);
        *(float2*)(ps + (wm * 16 + gid + 8) * 68 + ocol) =
            make_float2(oacc[nt][2], oacc[nt][3]);
    }
    __syncthreads();
    {
        const float OS = 0.022097086912079608f;   // 2048^-0.5
        const int r = tid >> 1;
        const int seg = (tid & 1) * 32;
        const float* pr = ps + r * 68 + seg;
        float* dst = out + ((size_t)b * S_ + s0 + r) * D_ + h * DH + seg;
#pragma unroll
        for (int v = 0; v < 8; v++) {
            float4 o4 = make_float4(pr[v*4+0] * OS, pr[v*4+1] * OS,
                                    pr[v*4+2] * OS, pr[v*4+3] * OS);
            *(float4*)(dst + v * 4) = o4;
        }
    }
}

// ---------------------------------------------------------------------------
extern "C" void kernel_launch(void* const* d_in, const int* in_sizes, int n_in,
                              void* d_out, int out_size)
{
    const float* x    = (const float*)d_in[0];
    const float* W    = (const float*)d_in[1];
    const float* bias = (const float*)d_in[2];
    float* out = (float*)d_out;

    cudaFuncSetAttribute(proj_kernel,
                         cudaFuncAttributeMaxDynamicSharedMemorySize, PJ_SMEM);
    cudaFuncSetAttribute(attn_kernel,
                         cudaFuncAttributeMaxDynamicSharedMemorySize, AT_SMEM);

    const int cvt_blocks = (int)((XB16 + WB16 + 255) / 256);
    cvt_kernel<<<cvt_blocks, 256>>>(x, W);

    dim3 pg(D_ * 2 / 128, (B_ * S_) / 128);          // (16, 64)
    proj_kernel<<<pg, 256, PJ_SMEM>>>(bias);

    ksum1_kernel<<<256, 256>>>();
    ksum2_kernel<<<64, 64>>>();

    dim3 ag(S_ / 128, H_, B_);                       // (16, 16, 4)
    attn_kernel<<<ag, 256, AT_SMEM>>>(out);
}

// round 11
// speedup vs baseline: 1.4425x; 1.4425x over previous
#include <cuda_runtime.h>
#include <cuda_fp16.h>
#include <cstdint>

#define B_  4
#define S_  2048
#define D_  1024
#define H_  16
#define DH  64

// Scratch (device globals -- no allocations allowed).
// k-dims stored with perm16: within each 16-block, memory position
// 4t+r (t=0..3, r=0..3) holds dim 2t + r + (r>=2 ? 6 : 0).
__device__ __half g_qh[(size_t)B_*H_*S_*DH];     // perm16 q
__device__ __half g_kh[(size_t)B_*H_*S_*DH];     // perm16 k (then folded k')
__device__ __half g_vh[(size_t)B_*H_*DH*S_];     // V^T: [bh][d][j perm16]
__device__ __half g_xh[(size_t)B_*S_*D_];        // perm16 x
__device__ __half g_wh[(size_t)2*D_*D_];         // perm16 W
__device__ float  g_kpart[256*64];
__device__ float  g_ksum[B_*H_*DH];              // perm16 layout

// ---------------------------------------------------------------------------
// helpers
// ---------------------------------------------------------------------------
__device__ __forceinline__ uint32_t smem_u32(const void* p) {
    uint32_t a;
    asm("{ .reg .u64 t; cvta.to.shared.u64 t, %1; cvt.u32.u64 %0, t; }"
        : "=r"(a) : "l"(p));
    return a;
}
#define CP_ASYNC16(dst, src) \
    asm volatile("cp.async.cg.shared.global [%0], [%1], 16;" :: "r"(dst), "l"(src) : "memory")
#define CP_COMMIT() asm volatile("cp.async.commit_group;" ::: "memory")
#define CP_WAIT(N)  asm volatile("cp.async.wait_group %0;" :: "n"(N) : "memory")

// fp16 mma m16n8k16 (row.col), fp32 accum, D += A*B
__device__ __forceinline__ void mma_f16(float* d, const uint32_t* a, const uint32_t* b)
{
    asm volatile(
        "mma.sync.aligned.m16n8k16.row.col.f32.f16.f16.f32 "
        "{%0,%1,%2,%3}, {%4,%5,%6,%7}, {%8,%9}, {%0,%1,%2,%3};"
        : "+f"(d[0]), "+f"(d[1]), "+f"(d[2]), "+f"(d[3])
        : "r"(a[0]), "r"(a[1]), "r"(a[2]), "r"(a[3]), "r"(b[0]), "r"(b[1]));
}

// selu on a pair of QK' accumulators (d = log2e * s):
//   selu(s) = lam*s (s>0) ;  lam*alpha*(2^d - 1) (s<=0)
//           = (lam*ln2)*max(d,0) + lam*alpha*(exp2(min(d,0)) - 1)
__device__ __forceinline__ uint32_t seluh2(float d0, float d1)
{
    const __half2 z   = __float2half2_rn(0.f);
    const __half2 la  = __float2half2_rn(1.7580993408473766f);    // lam*alpha
    const __half2 nla = __float2half2_rn(-1.7580993408473766f);
    const __half2 cp  = __float2half2_rn(0.72829048f);            // lam*ln2
    __half2 hd = __floats2half2_rn(d0, d1);
    __half2 dmin = __hmin2(hd, z);
    __half2 dmax = __hmax2(hd, z);
    __half2 e = h2exp2(dmin);
    __half2 r = __hfma2(la, e, nla);
    r = __hfma2(cp, dmax, r);
    return *reinterpret_cast<uint32_t*>(&r);
}

__device__ __forceinline__ int orig16(int r)    // perm16 inverse map
{
    const int t = r >> 2, m = r & 3;
    return 2 * t + m + ((m >= 2) ? 6 : 0);
}

// ---------------------------------------------------------------------------
// Kernel 0: fp16 + perm16 convert x and W
// ---------------------------------------------------------------------------
#define XB16 ((size_t)B_*S_*D_/16)       // 524288
#define WB16 ((size_t)2*D_*D_/16)        // 131072

__global__ __launch_bounds__(256) void cvt_kernel(
    const float* __restrict__ x, const float* __restrict__ W)
{
    const size_t i = (size_t)blockIdx.x * 256 + threadIdx.x;
    const float* src; __half* dst;
    if (i < XB16)              { src = x + i * 16;           dst = g_xh + i * 16; }
    else if (i < XB16 + WB16)  { src = W + (i - XB16) * 16;  dst = g_wh + (i - XB16) * 16; }
    else return;
    float v[16];
#pragma unroll
    for (int q = 0; q < 4; q++) *(float4*)&v[q*4] = *(const float4*)(src + q*4);
    __half h[16];
#pragma unroll
    for (int q = 0; q < 16; q++) h[q] = __float2half(v[orig16(q)]);
    *(uint4*)dst       = *(uint4*)&h[0];
    *(uint4*)(dst + 8) = *(uint4*)&h[8];
}

// ---------------------------------------------------------------------------
// Kernel 0b: V^T fp16 with j-perm16: g_vh[bh][d][p] = x[b][jmap(p)][h*64+d]
// ---------------------------------------------------------------------------
__global__ __launch_bounds__(256) void vtr_kernel(const float* __restrict__ x)
{
    __shared__ float t[128][65];
    const int b = blockIdx.z, h = blockIdx.y, j0 = blockIdx.x * 128;
    const int tid = threadIdx.x;
#pragma unroll
    for (int i = 0; i < 8; i++) {
        const int idx = tid + i * 256;
        const int row = idx >> 4, c4 = (idx & 15) * 4;
        float4 v = *(const float4*)(x + ((size_t)b * S_ + j0 + row) * D_ + h * 64 + c4);
        t[row][c4 + 0] = v.x; t[row][c4 + 1] = v.y;
        t[row][c4 + 2] = v.z; t[row][c4 + 3] = v.w;
    }
    __syncthreads();
    const int d = tid >> 2;
    const int pg = (tid & 3) * 32;
    __half* dst = g_vh + ((size_t)(b * H_ + h) * DH + d) * S_ + j0 + pg;
#pragma unroll
    for (int u = 0; u < 4; u++) {
        __half h8[8];
#pragma unroll
        for (int q = 0; q < 8; q++) {
            const int p = pg + u * 8 + q;
            const int j = (p & ~15) + orig16(p & 15);
            h8[q] = __float2half(t[j][d]);
        }
        *(uint4*)(dst + u * 8) = *(uint4*)h8;
    }
}

// ---------------------------------------------------------------------------
// Kernel 1: fused q/k projection, fp16 m16n8k16, 2-stage (R9-proven).
// ---------------------------------------------------------------------------
#define PJ_LDH   48
#define PJ_MAT_B (128 * 96)
#define PJ_STG_B (2 * PJ_MAT_B)              // 24576 B per stage
#define PJ_SMEM  67584
#define PJ_LDC   132

__global__ __launch_bounds__(256, 2) void proj_kernel(const float* __restrict__ bias)
{
    extern __shared__ char smc[];
    float* Cs = (float*)smc;
    __shared__ float sBias[128];

    const int tid = threadIdx.x;
    const int m0 = blockIdx.y * 128;
    const int n0 = blockIdx.x * 128;
    const int wid = tid >> 5;
    const int lane = tid & 31;
    const int gid = lane >> 2;
    const int tig = lane & 3;
    const int wm = wid & 1;
    const int wn = wid >> 1;

    if (tid < 128) sBias[tid] = bias[n0 + tid];

    float acc[4][4][4];
#pragma unroll
    for (int mi = 0; mi < 4; mi++)
#pragma unroll
        for (int ni = 0; ni < 4; ni++)
#pragma unroll
            for (int r = 0; r < 4; r++) acc[mi][ni][r] = 0.f;

    const uint32_t sbase = smem_u32(smc);

    auto load_stage = [&](int s, int k0) {
        const uint32_t aB = sbase + s * PJ_STG_B;
        const uint32_t bB = aB + PJ_MAT_B;
#pragma unroll
        for (int i = 0; i < 2; i++) {
            const int idx = tid + i * 256;
            const int row = idx >> 2, c = idx & 3;
            CP_ASYNC16(aB + row * 96 + c * 16,
                       g_xh + (size_t)(m0 + row) * D_ + k0 + c * 8);
        }
#pragma unroll
        for (int i = 0; i < 2; i++) {
            const int idx = tid + i * 256;
            const int row = idx >> 2, c = idx & 3;
            CP_ASYNC16(bB + row * 96 + c * 16,
                       g_wh + (size_t)(n0 + row) * D_ + k0 + c * 8);
        }
        CP_COMMIT();
    };

    load_stage(0, 0);
    load_stage(1, 32);

    const int NKC = D_ / 32;
    for (int kc = 0; kc < NKC; kc++) {
        if (kc < NKC - 1) CP_WAIT(1); else CP_WAIT(0);
        __syncthreads();

        const __half* A  = (const __half*)(smc + (kc & 1) * PJ_STG_B);
        const __half* Bp = A + 128 * PJ_LDH;
#pragma unroll
        for (int kg = 0; kg < 2; kg++) {
            uint32_t a[4][4];
#pragma unroll
            for (int mi = 0; mi < 4; mi++) {
                const __half* ra = A + (wm * 64 + mi * 16 + gid) * PJ_LDH + kg * 16 + tig * 4;
                uint2 lo = *(const uint2*)ra;
                uint2 hi = *(const uint2*)(ra + 8 * PJ_LDH);
                a[mi][0] = lo.x; a[mi][1] = hi.x; a[mi][2] = lo.y; a[mi][3] = hi.y;
            }
            uint32_t bf[4][2];
#pragma unroll
            for (int ni = 0; ni < 4; ni++) {
                const __half* rb = Bp + (wn * 32 + ni * 8 + gid) * PJ_LDH + kg * 16 + tig * 4;
                uint2 f = *(const uint2*)rb;
                bf[ni][0] = f.x; bf[ni][1] = f.y;
            }
#pragma unroll
            for (int mi = 0; mi < 4; mi++)
#pragma unroll
                for (int ni = 0; ni < 4; ni++)
                    mma_f16(acc[mi][ni], a[mi], bf[ni]);
        }
        __syncthreads();
        if (kc + 2 < NKC) load_stage(kc & 1, (kc + 2) * 32);
    }

    // ---- epilogue: acc -> Cs -> perm16 fp16 scatter to g_qh / g_kh ----
#pragma unroll
    for (int mi = 0; mi < 4; mi++)
#pragma unroll
        for (int ni = 0; ni < 4; ni++) {
            const int r = wm * 64 + mi * 16 + gid;
            const int c = wn * 32 + ni * 8 + 2 * tig;
            *(float2*)&Cs[r * PJ_LDC + c]       = make_float2(acc[mi][ni][0], acc[mi][ni][1]);
            *(float2*)&Cs[(r + 8) * PJ_LDC + c] = make_float2(acc[mi][ni][2], acc[mi][ni][3]);
        }
    __syncthreads();

    {
        const int r    = tid >> 1;
        const int hsel = tid & 1;
        const int m = m0 + r;
        const int bb = m >> 11;
        const int s_idx = m & 2047;
        const int hh = n0 >> 7;
        const size_t base = (((size_t)bb * H_ + hh) * S_ + s_idx) * DH;
        const float* cr = Cs + r * PJ_LDC;
#pragma unroll
        for (int bi = 0; bi < 2; bi++) {
            const int bk = hsel * 2 + bi;
            __half qh[16], kh[16];
#pragma unroll
            for (int q = 0; q < 16; q++) {
                const int dorig = bk * 16 + orig16(q);
                qh[q] = __float2half(cr[2 * dorig]     + sBias[2 * dorig]);
                kh[q] = __float2half(cr[2 * dorig + 1] + sBias[2 * dorig + 1]);
            }
            *(uint4*)(g_qh + base + bk * 16)     = *(uint4*)&qh[0];
            *(uint4*)(g_qh + base + bk * 16 + 8) = *(uint4*)&qh[8];
            *(uint4*)(g_kh + base + bk * 16)     = *(uint4*)&kh[0];
            *(uint4*)(g_kh + base + bk * 16 + 8) = *(uint4*)&kh[8];
        }
    }
}

// ---------------------------------------------------------------------------
// Kernel 2: ksum, then fold mean + scale*log2e into K in place:
//   k' = (k - ksum/S) * (SCALE * log2e)
// ---------------------------------------------------------------------------
__global__ __launch_bounds__(256) void ksum1_kernel()
{
    __shared__ float red[256];
    const int blk = blockIdx.x;
    const int bh = blk >> 2, c = blk & 3;
    const int t = threadIdx.x;
    const int d = t & 63;
    const int sub = t >> 6;
    const __half* base = g_kh + (size_t)bh * S_ * DH;
    const int j0 = c * 512 + sub * 128, j1 = j0 + 128;
    float s = 0.f;
    for (int j = j0; j < j1; j++) s += __half2float(base[(size_t)j * DH + d]);
    red[t] = s;
    __syncthreads();
    if (t < 64)
        g_kpart[blk * 64 + t] = red[t] + red[64 + t] + red[128 + t] + red[192 + t];
}

__global__ __launch_bounds__(64) void ksum2_kernel()
{
    const int bh = blockIdx.x;
    const int d = threadIdx.x;
    g_ksum[bh * 64 + d] = g_kpart[(bh * 4 + 0) * 64 + d] + g_kpart[(bh * 4 + 1) * 64 + d]
                        + g_kpart[(bh * 4 + 2) * 64 + d] + g_kpart[(bh * 4 + 3) * 64 + d];
}

__global__ __launch_bounds__(256) void kadj_kernel()
{
    __shared__ float sk[64];
    const int bh  = blockIdx.y;
    const int seg = blockIdx.x;              // 0..7, 256 rows each
    const int tid = threadIdx.x;
    if (tid < 64) sk[tid] = g_ksum[bh * 64 + tid] * (1.f / (float)S_);
    __syncthreads();
    const float KF = 0.125f * 1.4426950408889634f;   // SCALE * log2(e)
    __half* base = g_kh + (size_t)bh * S_ * DH + (size_t)seg * 256 * DH;
    for (int i = tid; i < 2048; i += 256) {          // 2048 uint4 = 16384 halves
        __half h[8];
        *(uint4*)h = *(const uint4*)(base + i * 8);
        const int p0 = (i * 8) & 63;
#pragma unroll
        for (int q = 0; q < 8; q++)
            h[q] = __float2half((__half2float(h[q]) - sk[p0 + q]) * KF);
        *(uint4*)(base + i * 8) = *(uint4*)h;
    }
}

// ---------------------------------------------------------------------------
// Kernel 3: fused attention, fp16 m16n8k16, mean pre-folded into K.
// 256 threads, 2 CTAs/SM.  8 warps: wm = wid (16 q-rows, full j=64 per iter).
// QK' accumulator d = log2e*s; selu evaluated in half2 (seluh2).
// smem: qs 128x80h (20480), ks 2x64x80h, vs 2x64x80h, ps 128x68 f32.
// ---------------------------------------------------------------------------
#define AT_LDH  80
#define AT_QS_B (128 * AT_LDH * 2)           // 20480
#define AT_KS_B (64 * AT_LDH * 2)            // 10240
#define AT_PS_OFF (AT_QS_B + 4 * AT_KS_B)    // 61440
#define AT_SMEM (AT_PS_OFF + 128 * 68 * 4)   // 96256

__global__ __launch_bounds__(256, 2) void attn_kernel(float* __restrict__ out)
{
    extern __shared__ char smc[];
    __half* qs  = (__half*)smc;
    __half* ksb = (__half*)(smc + AT_QS_B);
    __half* vsb = (__half*)(smc + AT_QS_B + 2 * AT_KS_B);
    float*  ps  = (float*)(smc + AT_PS_OFF);

    const int b  = blockIdx.z;
    const int h  = blockIdx.y;
    const int s0 = blockIdx.x * 128;
    const int tid = threadIdx.x;
    const int wid = tid >> 5;
    const int lane = tid & 31;
    const int gid = lane >> 2;
    const int tig = lane & 3;
    const int wm = wid;

    const size_t bh = (size_t)b * H_ + h;
    const __half* qg = g_qh + bh * S_ * DH;
    const __half* kg = g_kh + bh * S_ * DH;
    const __half* vg = g_vh + bh * DH * S_;

    const uint32_t qsB = smem_u32(qs);
    const uint32_t ksB = smem_u32(ksb);
    const uint32_t vsB = smem_u32(vsb);

    auto load_kv = [&](int buf, int j0) {
        const uint32_t kB = ksB + buf * AT_KS_B;
        const uint32_t vB = vsB + buf * AT_KS_B;
#pragma unroll
        for (int i = 0; i < 2; i++) {
            const int idx = tid + i * 256;
            const int row = idx >> 3, c = idx & 7;
            CP_ASYNC16(kB + row * 160 + c * 16,
                       kg + (size_t)(j0 + row) * DH + c * 8);
        }
#pragma unroll
        for (int i = 0; i < 2; i++) {
            const int idx = tid + i * 256;
            const int row = idx >> 3, c = idx & 7;   // row = d
            CP_ASYNC16(vB + row * 160 + c * 16,
                       vg + (size_t)row * S_ + j0 + c * 8);
        }
    };

    // ---- prologue: Q + K/V tile 0 ----
#pragma unroll
    for (int i = 0; i < 4; i++) {
        const int idx = tid + i * 256;
        const int row = idx >> 3, c = idx & 7;
        CP_ASYNC16(qsB + row * 160 + c * 16,
                   qg + (size_t)(s0 + row) * DH + c * 8);
    }
    load_kv(0, 0);
    CP_COMMIT();

    float oacc[8][4];
#pragma unroll
    for (int nt = 0; nt < 8; nt++)
#pragma unroll
        for (int r = 0; r < 4; r++) oacc[nt][r] = 0.f;

    const int NJT = S_ / 64;                 // 32
    for (int jt = 0; jt < NJT; jt++) {
        const int buf = jt & 1;
        CP_WAIT(0);
        __syncthreads();                     // K/V[buf] ready; prior reads of buf^1 done
        if (jt + 1 < NJT) {
            load_kv(buf ^ 1, (jt + 1) * 64);
            CP_COMMIT();
        }

        const __half* kss = ksb + buf * (64 * AT_LDH);
        const __half* vss = vsb + buf * (64 * AT_LDH);

        // ---- d = Q K'^T : 16m x 64j  (d = log2e * (scale*qk - mean)) ----
        float d[8][4];
#pragma unroll
        for (int tn = 0; tn < 8; tn++)
#pragma unroll
            for (int r = 0; r < 4; r++) d[tn][r] = 0.f;

#pragma unroll
        for (int g = 0; g < 4; g++) {
            const __half* ra = qs + (wm * 16 + gid) * AT_LDH + g * 16 + tig * 4;
            uint2 lo = *(const uint2*)ra;
            uint2 hi = *(const uint2*)(ra + 8 * AT_LDH);
            uint32_t a[4] = { lo.x, hi.x, lo.y, hi.y };
#pragma unroll
            for (int tn = 0; tn < 8; tn++) {
                const __half* rb = kss + (tn * 8 + gid) * AT_LDH + g * 16 + tig * 4;
                uint2 f = *(const uint2*)rb;
                uint32_t bb2[2] = { f.x, f.y };
                mma_f16(d[tn], a, bb2);
            }
        }

        // ---- half2 selu; packs feed AV A-fragments directly ----
        uint32_t av[4][4];
#pragma unroll
        for (int u = 0; u < 4; u++) {
            av[u][0] = seluh2(d[2*u][0],   d[2*u][1]);     // row gid,   k 2tig..
            av[u][1] = seluh2(d[2*u][2],   d[2*u][3]);     // row gid+8
            av[u][2] = seluh2(d[2*u+1][0], d[2*u+1][1]);   // row gid,   k 2tig+8..
            av[u][3] = seluh2(d[2*u+1][2], d[2*u+1][3]);   // row gid+8
        }

        // ---- oacc += A @ V  (V^T j-perm16 fragments) ----
#pragma unroll
        for (int nt = 0; nt < 8; nt++) {
#pragma unroll
            for (int u = 0; u < 4; u++) {
                const __half* rv = vss + (nt * 8 + gid) * AT_LDH + u * 16 + tig * 4;
                uint2 f = *(const uint2*)rv;
                uint32_t bb2[2] = { f.x, f.y };
                mma_f16(oacc[nt], av[u], bb2);
            }
        }
    }

    // ---- epilogue: oacc -> ps -> coalesced gmem ----
    __syncthreads();
#pragma unroll
    for (int nt = 0; nt < 8; nt++) {
        *(float2*)(ps + (wm * 16 + gid) * 68 + nt * 8 + 2 * tig) =
            make_float2(oacc[nt][0], oacc[nt][1]);
        *(float2*)(ps + (wm * 16 + gid + 8) * 68 + nt * 8 + 2 * tig) =
            make_float2(oacc[nt][2], oacc[nt][3]);
    }
    __syncthreads();
    {
        const float OS = 0.022097086912079608f;   // 2048^-0.5
        const int r = tid >> 1;
        const int seg = (tid & 1) * 32;
        const float* pr = ps + r * 68 + seg;
        float* dst = out + ((size_t)b * S_ + s0 + r) * D_ + h * DH + seg;
#pragma unroll
        for (int v = 0; v < 8; v++) {
            float4 o4 = make_float4(pr[v*4+0] * OS, pr[v*4+1] * OS,
                                    pr[v*4+2] * OS, pr[v*4+3] * OS);
            *(float4*)(dst + v * 4) = o4;
        }
    }
}

// ---------------------------------------------------------------------------
extern "C" void kernel_launch(void* const* d_in, const int* in_sizes, int n_in,
                              void* d_out, int out_size)
{
    const float* x    = (const float*)d_in[0];
    const float* W    = (const float*)d_in[1];
    const float* bias = (const float*)d_in[2];
    float* out = (float*)d_out;

    cudaFuncSetAttribute(proj_kernel,
                         cudaFuncAttributeMaxDynamicSharedMemorySize, PJ_SMEM);
    cudaFuncSetAttribute(attn_kernel,
                         cudaFuncAttributeMaxDynamicSharedMemorySize, AT_SMEM);

    const int cvt_blocks = (int)((XB16 + WB16 + 255) / 256);
    cvt_kernel<<<cvt_blocks, 256>>>(x, W);

    dim3 vg(S_ / 128, H_, B_);                       // (16, 16, 4)
    vtr_kernel<<<vg, 256>>>(x);

    dim3 pg(D_ * 2 / 128, (B_ * S_) / 128);          // (16, 64)
    proj_kernel<<<pg, 256, PJ_SMEM>>>(bias);

    ksum1_kernel<<<256, 256>>>();
    ksum2_kernel<<<64, 64>>>();

    dim3 kg(8, B_ * H_);                             // (8, 64)
    kadj_kernel<<<kg, 256>>>();

    dim3 ag(S_ / 128, H_, B_);                       // (16, 16, 4)
    attn_kernel<<<ag, 256, AT_SMEM>>>(out);
}